// round 1
// baseline (speedup 1.0000x reference)
#include <cuda_runtime.h>
#include <math.h>

#define N_NODES 50000
#define N_EDGES 800000
#define FIN0 16
#define DM 96
#define NG 64

// ---------------- device scratch (no allocations allowed) ----------------
__device__ float g_h[N_NODES * DM];     // post-GEMM (X @ W)
__device__ float g_agg[N_NODES * DM];   // aggregated output of a conv layer
__device__ float g_dis[N_NODES];        // deg^{-1/2}
__device__ int   g_deg[N_NODES];
__device__ float g_gmax[NG * DM];
__device__ float g_gsum[NG * DM];
__device__ float g_cnt[NG];
__device__ float g_pooled[NG * 2 * DM];
__device__ float g_hidden[NG * DM];
__device__ int   g_is64;                // 1 if indices are int64, 0 if int32

__device__ __forceinline__ float lrelu(float v) { return v > 0.0f ? v : 0.01f * v; }

__device__ __forceinline__ long long read_idx(const void* p, long long i) {
    if (g_is64) return ((const long long*)p)[i];
    return (long long)((const int*)p)[i];
}

// ---------------- dtype detection -----------------------------------------
// int64 little-endian values < 2^31 -> every odd 32-bit word is 0.
// genuine int32 index data (uniform in [0,50000)) is ~never all-zero there.
__global__ void detect_dtype_k(const int* __restrict__ ei32) {
    __shared__ int nz;
    if (threadIdx.x == 0) nz = 0;
    __syncthreads();
    for (int i = threadIdx.x; i < 4096; i += blockDim.x) {
        if (ei32[2 * i + 1] != 0) atomicAdd(&nz, 1);
    }
    __syncthreads();
    if (threadIdx.x == 0) g_is64 = (nz == 0) ? 1 : 0;
}

// ---------------- degree / norm -------------------------------------------
__global__ void deg_init_k() {
    int i = blockIdx.x * blockDim.x + threadIdx.x;
    if (i < N_NODES) g_deg[i] = 1;  // self-loop
}

__global__ void deg_count_k(const void* __restrict__ ei) {
    int e = blockIdx.x * blockDim.x + threadIdx.x;
    if (e < N_EDGES) {
        int d = (int)read_idx(ei, (long long)N_EDGES + e);  // dst row
        atomicAdd(&g_deg[d], 1);
    }
}

__global__ void dis_k() {
    int i = blockIdx.x * blockDim.x + threadIdx.x;
    if (i < N_NODES) g_dis[i] = rsqrtf((float)g_deg[i]);
}

// ---------------- GEMM: g_h = act(X) @ W ----------------------------------
template <int FIN, bool RELU_IN, int NODES_PER_BLK>
__global__ void gemm_k(const float* __restrict__ X, const float* __restrict__ W) {
    __shared__ float Ws[FIN * DM];
    __shared__ float Xs[NODES_PER_BLK * FIN];
    int node0 = blockIdx.x * NODES_PER_BLK;
    int nn = N_NODES - node0;
    if (nn > NODES_PER_BLK) nn = NODES_PER_BLK;

    for (int i = threadIdx.x; i < FIN * DM; i += blockDim.x) Ws[i] = W[i];
    for (int i = threadIdx.x; i < nn * FIN; i += blockDim.x) {
        float v = X[(size_t)node0 * FIN + i];
        Xs[i] = RELU_IN ? lrelu(v) : v;
    }
    __syncthreads();

    for (int o = threadIdx.x; o < nn * DM; o += blockDim.x) {
        int r = o / DM, j = o % DM;
        float acc = 0.0f;
#pragma unroll 16
        for (int k = 0; k < FIN; k++) acc = fmaf(Xs[r * FIN + k], Ws[k * DM + j], acc);
        g_h[(size_t)(node0 + r) * DM + j] = acc;
    }
}

// ---------------- agg init: bias + self-loop term --------------------------
__global__ void agg_init_k(const float* __restrict__ b) {
    int i = blockIdx.x * blockDim.x + threadIdx.x;
    if (i < N_NODES * DM) {
        int n = i / DM, f = i % DM;
        float d = g_dis[n];
        g_agg[i] = b[f] + g_h[i] * d * d;
    }
}

// ---------------- edge scatter: warp per edge -------------------------------
__global__ void scatter_k(const void* __restrict__ ei) {
    int w = (blockIdx.x * blockDim.x + threadIdx.x) >> 5;
    int lane = threadIdx.x & 31;
    if (w >= N_EDGES) return;
    int s = (int)read_idx(ei, w);
    int d = (int)read_idx(ei, (long long)N_EDGES + w);
    float norm = g_dis[s] * g_dis[d];
    const float* hs = g_h + (size_t)s * DM;
    float* ag = g_agg + (size_t)d * DM;
#pragma unroll
    for (int f = lane; f < DM; f += 32) {
        atomicAdd(&ag[f], hs[f] * norm);
    }
}

// ---------------- pooling ---------------------------------------------------
__device__ __forceinline__ void atomicMaxFloat(float* addr, float v) {
    if (v >= 0.0f) atomicMax((int*)addr, __float_as_int(v));
    else           atomicMin((unsigned int*)addr, __float_as_uint(v));
}

__global__ void pool_init_k() {
    int i = blockIdx.x * blockDim.x + threadIdx.x;
    if (i < NG * DM) {
        g_gmax[i] = -INFINITY;
        g_gsum[i] = 0.0f;
    }
    if (i < NG) g_cnt[i] = 0.0f;
}

__global__ void pool_k(const void* __restrict__ batch) {
    int i = blockIdx.x * blockDim.x + threadIdx.x;
    if (i >= N_NODES * DM) return;
    int n = i / DM, f = i % DM;
    int g = (int)read_idx(batch, n);
    float v = lrelu(g_agg[i]);
    atomicAdd(&g_gsum[g * DM + f], v);
    atomicMaxFloat(&g_gmax[g * DM + f], v);
    if (f == 0) atomicAdd(&g_cnt[g], 1.0f);
}

__global__ void pooled_k() {
    int i = blockIdx.x * blockDim.x + threadIdx.x;
    if (i >= NG * DM) return;
    int g = i / DM, f = i % DM;
    g_pooled[g * 2 * DM + f] = g_gmax[i];
    g_pooled[g * 2 * DM + DM + f] = g_gsum[i] / fmaxf(g_cnt[g], 1.0f);
}

// ---------------- MLP head --------------------------------------------------
__global__ void mlp1_k(const float* __restrict__ Wo1, const float* __restrict__ bo1) {
    int g = blockIdx.x;
    int j = threadIdx.x;  // 96 threads
    float acc = bo1[j];
#pragma unroll 8
    for (int k = 0; k < 2 * DM; k++) acc = fmaf(g_pooled[g * 2 * DM + k], Wo1[k * DM + j], acc);
    g_hidden[g * DM + j] = lrelu(acc);
}

__global__ void mlp2_k(const float* __restrict__ Wo2, const float* __restrict__ bo2,
                       float* __restrict__ out) {
    int g = blockIdx.x * blockDim.x + threadIdx.x;
    if (g >= NG) return;
    float acc = bo2[0];
#pragma unroll 8
    for (int k = 0; k < DM; k++) acc = fmaf(g_hidden[g * DM + k], Wo2[k], acc);
    out[g] = acc;
}

// ---------------- host orchestration ---------------------------------------
extern "C" void kernel_launch(void* const* d_in, const int* in_sizes, int n_in,
                              void* d_out, int out_size) {
    const float* x      = (const float*)d_in[0];
    const void*  ei     = d_in[1];
    const void*  batch  = d_in[2];
    const float* W_init = (const float*)d_in[3];
    const float* b_init = (const float*)d_in[4];
    const float* Wl[4]  = {(const float*)d_in[5], (const float*)d_in[7],
                           (const float*)d_in[9], (const float*)d_in[11]};
    const float* bl[4]  = {(const float*)d_in[6], (const float*)d_in[8],
                           (const float*)d_in[10], (const float*)d_in[12]};
    const float* Wo1    = (const float*)d_in[13];
    const float* bo1    = (const float*)d_in[14];
    const float* Wo2    = (const float*)d_in[15];
    const float* bo2    = (const float*)d_in[16];
    float* out = (float*)d_out;

    float* p_agg = nullptr;
    cudaGetSymbolAddress((void**)&p_agg, g_agg);

    const int T = 256;
    const int gridN   = (N_NODES + T - 1) / T;
    const int gridE   = (N_EDGES + T - 1) / T;
    const int gridNF  = (N_NODES * DM + T - 1) / T;
    const int gridSc  = (N_EDGES * 32 + T - 1) / T;
    const int NODES_PER_BLK = 24;
    const int gridGemm = (N_NODES + NODES_PER_BLK - 1) / NODES_PER_BLK;

    detect_dtype_k<<<1, 256>>>((const int*)ei);
    deg_init_k<<<gridN, T>>>();
    deg_count_k<<<gridE, T>>>(ei);
    dis_k<<<gridN, T>>>();

    // layer 1 (FIN=16, no input activation)
    gemm_k<FIN0, false, NODES_PER_BLK><<<gridGemm, T>>>(x, W_init);
    agg_init_k<<<gridNF, T>>>(b_init);
    scatter_k<<<gridSc, T>>>(ei);

    // layers 2..5 (FIN=96, leaky-relu applied to g_agg on load)
    for (int l = 0; l < 4; l++) {
        gemm_k<DM, true, NODES_PER_BLK><<<gridGemm, T>>>(p_agg, Wl[l]);
        agg_init_k<<<gridNF, T>>>(bl[l]);
        scatter_k<<<gridSc, T>>>(ei);
    }

    // pooling (applies final leaky-relu)
    pool_init_k<<<(NG * DM + T - 1) / T, T>>>();
    pool_k<<<gridNF, T>>>(batch);
    pooled_k<<<(NG * DM + T - 1) / T, T>>>();

    // MLP head
    mlp1_k<<<NG, DM>>>(Wo1, bo1);
    mlp2_k<<<1, NG>>>(Wo2, bo2, out);
}

// round 4
// speedup vs baseline: 2.5313x; 2.5313x over previous
#include <cuda_runtime.h>
#include <math.h>

#define N_NODES 50000
#define N_EDGES 800000
#define FIN0 16
#define DM 96
#define NG 64
#define NBLK_N 196   // ceil(50000/256)

// ---------------- device scratch (no allocations allowed) ----------------
__device__ float g_h[N_NODES * DM];       // post-GEMM (X @ W)
__device__ float g_agg[N_NODES * DM];     // conv output (leaky-relu applied)
__device__ float g_dis[N_NODES];          // deg^{-1/2}
__device__ int   g_deg[N_NODES];          // includes self-loop
__device__ int   g_rowstart[N_NODES + 1]; // CSR by destination (real edges only)
__device__ int   g_cursor[N_NODES];
__device__ int   g_bsum[NBLK_N];
__device__ int   g_boff[NBLK_N];
__device__ int   g_csr_src[N_EDGES];
__device__ float g_csr_norm[N_EDGES];
__device__ int   g_gcnt[NG];
__device__ int   g_goff[NG + 1];
__device__ float g_pooled[NG * 2 * DM];
__device__ float g_hidden[NG * DM];
__device__ int   g_is64;

__device__ __forceinline__ float lrelu(float v) { return v > 0.0f ? v : 0.01f * v; }

__device__ __forceinline__ long long read_idx(const void* p, long long i) {
    if (g_is64) return ((const long long*)p)[i];
    return (long long)((const int*)p)[i];
}

// ---------------- dtype detection -----------------------------------------
__global__ void detect_dtype_k(const int* __restrict__ ei32) {
    __shared__ int nz;
    if (threadIdx.x == 0) nz = 0;
    __syncthreads();
    for (int i = threadIdx.x; i < 4096; i += blockDim.x)
        if (ei32[2 * i + 1] != 0) atomicAdd(&nz, 1);
    __syncthreads();
    if (threadIdx.x == 0) g_is64 = (nz == 0) ? 1 : 0;
}

// ---------------- degree / norm -------------------------------------------
__global__ void deg_init_k() {
    int i = blockIdx.x * blockDim.x + threadIdx.x;
    if (i < N_NODES) g_deg[i] = 1;  // self-loop
    if (i < NG) g_gcnt[i] = 0;
}

__global__ void deg_count_k(const void* __restrict__ ei) {
    int e = blockIdx.x * blockDim.x + threadIdx.x;
    if (e < N_EDGES) atomicAdd(&g_deg[(int)read_idx(ei, (long long)N_EDGES + e)], 1);
}

__global__ void dis_k() {
    int i = blockIdx.x * blockDim.x + threadIdx.x;
    if (i < N_NODES) g_dis[i] = rsqrtf((float)g_deg[i]);
}

// ---------------- CSR build: 2-level scan + bucket scatter ------------------
__global__ void scan_part_k() {
    __shared__ int sm[256];
    int i = blockIdx.x * 256 + threadIdx.x;
    sm[threadIdx.x] = (i < N_NODES) ? g_deg[i] - 1 : 0;
    __syncthreads();
    for (int off = 128; off > 0; off >>= 1) {
        if (threadIdx.x < off) sm[threadIdx.x] += sm[threadIdx.x + off];
        __syncthreads();
    }
    if (threadIdx.x == 0) g_bsum[blockIdx.x] = sm[0];
}

__global__ void scan_top_k() {
    __shared__ int s[256];
    int t = threadIdx.x;
    int own = (t < NBLK_N) ? g_bsum[t] : 0;
    s[t] = own;
    __syncthreads();
    for (int off = 1; off < 256; off <<= 1) {
        int v = (t >= off) ? s[t - off] : 0;
        __syncthreads();
        s[t] += v;
        __syncthreads();
    }
    if (t < NBLK_N) g_boff[t] = s[t] - own;
    if (t == 0) g_rowstart[N_NODES] = N_EDGES;
}

__global__ void scan_down_k() {
    __shared__ int sm[256];
    int t = threadIdx.x;
    int i = blockIdx.x * 256 + t;
    int v = (i < N_NODES) ? g_deg[i] - 1 : 0;
    sm[t] = v;
    __syncthreads();
    for (int off = 1; off < 256; off <<= 1) {
        int u = (t >= off) ? sm[t - off] : 0;
        __syncthreads();
        sm[t] += u;
        __syncthreads();
    }
    if (i < N_NODES) {
        int rs = g_boff[blockIdx.x] + sm[t] - v;
        g_rowstart[i] = rs;
        g_cursor[i] = rs;
    }
}

__global__ void bucket_k(const void* __restrict__ ei) {
    int e = blockIdx.x * blockDim.x + threadIdx.x;
    if (e >= N_EDGES) return;
    int s = (int)read_idx(ei, e);
    int d = (int)read_idx(ei, (long long)N_EDGES + e);
    int pos = atomicAdd(&g_cursor[d], 1);
    g_csr_src[pos] = s;
    g_csr_norm[pos] = g_dis[s] * g_dis[d];
}

__global__ void gcnt_k(const void* __restrict__ batch) {
    int i = blockIdx.x * blockDim.x + threadIdx.x;
    if (i < N_NODES) atomicAdd(&g_gcnt[(int)read_idx(batch, i)], 1);
}

__global__ void goff_k() {
    __shared__ int s[NG];
    int t = threadIdx.x;  // 64 threads
    s[t] = g_gcnt[t];
    __syncthreads();
    for (int off = 1; off < NG; off <<= 1) {
        int v = (t >= off) ? s[t - off] : 0;
        __syncthreads();
        s[t] += v;
        __syncthreads();
    }
    g_goff[t + 1] = s[t];
    if (t == 0) g_goff[0] = 0;
}

// ---------------- GEMM: g_h = X @ W  (128x96 tile, 8x6 regs/thread) --------
template <int FIN>
__global__ void gemm_k(const float* __restrict__ X, const float* __restrict__ W) {
    __shared__ float Ws[FIN * DM];
    __shared__ float Xs[128 * FIN];
    int node0 = blockIdx.x * 128;
    int nn = N_NODES - node0;
    if (nn > 128) nn = 128;

    for (int i = threadIdx.x; i < FIN * DM; i += 256) Ws[i] = W[i];
    for (int i = threadIdx.x; i < nn * FIN; i += 256) Xs[i] = X[(size_t)node0 * FIN + i];
    __syncthreads();

    int c = (threadIdx.x & 15) * 6;   // column base (0..90)
    int r0 = (threadIdx.x >> 4) * 8;  // row base (0..120)
    float acc[8][6];
#pragma unroll
    for (int r = 0; r < 8; r++)
#pragma unroll
        for (int j = 0; j < 6; j++) acc[r][j] = 0.0f;

#pragma unroll 4
    for (int k = 0; k < FIN; k++) {
        float w0 = Ws[k * DM + c + 0], w1 = Ws[k * DM + c + 1], w2 = Ws[k * DM + c + 2];
        float w3 = Ws[k * DM + c + 3], w4 = Ws[k * DM + c + 4], w5 = Ws[k * DM + c + 5];
#pragma unroll
        for (int r = 0; r < 8; r++) {
            float xv = Xs[(r0 + r) * FIN + k];
            acc[r][0] = fmaf(xv, w0, acc[r][0]);
            acc[r][1] = fmaf(xv, w1, acc[r][1]);
            acc[r][2] = fmaf(xv, w2, acc[r][2]);
            acc[r][3] = fmaf(xv, w3, acc[r][3]);
            acc[r][4] = fmaf(xv, w4, acc[r][4]);
            acc[r][5] = fmaf(xv, w5, acc[r][5]);
        }
    }
#pragma unroll
    for (int r = 0; r < 8; r++) {
        int row = r0 + r;
        if (row < nn) {
            float* o = g_h + (size_t)(node0 + row) * DM + c;
#pragma unroll
            for (int j = 0; j < 6; j++) o[j] = acc[r][j];
        }
    }
}

// ---------------- gather: agg = lrelu(bias + self + sum_in norm*h[src]) -----
__global__ void gather_k(const float* __restrict__ b) {
    int w = (blockIdx.x * blockDim.x + threadIdx.x) >> 5;
    if (w >= N_NODES) return;
    int lane = threadIdx.x & 31;
    int beg = g_rowstart[w], end = g_rowstart[w + 1];
    float dn = g_dis[w];
    const float* hn = g_h + (size_t)w * DM;
    float a0 = fmaf(hn[lane], dn * dn, b[lane]);
    float a1 = fmaf(hn[lane + 32], dn * dn, b[lane + 32]);
    float a2 = fmaf(hn[lane + 64], dn * dn, b[lane + 64]);
    for (int j = beg; j < end; j++) {
        int s = __ldg(&g_csr_src[j]);
        float nm = __ldg(&g_csr_norm[j]);
        const float* hs = g_h + (size_t)s * DM;
        a0 = fmaf(hs[lane], nm, a0);
        a1 = fmaf(hs[lane + 32], nm, a1);
        a2 = fmaf(hs[lane + 64], nm, a2);
    }
    float* out = g_agg + (size_t)w * DM;
    out[lane] = lrelu(a0);
    out[lane + 32] = lrelu(a1);
    out[lane + 64] = lrelu(a2);
}

// ---------------- segmented pooling (batch_index sorted) --------------------
__global__ void pool_seg_k() {
    int g = blockIdx.x;
    int beg = g_goff[g], end = g_goff[g + 1];
    int f = threadIdx.x % DM, rr = threadIdx.x / DM;  // 288 threads = 3 x 96
    float mx = -INFINITY, sm = 0.0f;
    for (int n = beg + rr; n < end; n += 3) {
        float v = g_agg[(size_t)n * DM + f];
        mx = fmaxf(mx, v);
        sm += v;
    }
    __shared__ float smx[288], ssm[288];
    smx[threadIdx.x] = mx;
    ssm[threadIdx.x] = sm;
    __syncthreads();
    if (rr == 0) {
        mx = fmaxf(fmaxf(smx[f], smx[f + DM]), smx[f + 2 * DM]);
        sm = ssm[f] + ssm[f + DM] + ssm[f + 2 * DM];
        float cnt = (float)(end - beg);
        g_pooled[g * 2 * DM + f] = mx;
        g_pooled[g * 2 * DM + DM + f] = sm / fmaxf(cnt, 1.0f);
    }
}

// ---------------- MLP head --------------------------------------------------
__global__ void mlp1_k(const float* __restrict__ Wo1, const float* __restrict__ bo1) {
    int g = blockIdx.x;
    int j = threadIdx.x;  // 96 threads
    float acc = bo1[j];
#pragma unroll 8
    for (int k = 0; k < 2 * DM; k++) acc = fmaf(g_pooled[g * 2 * DM + k], Wo1[k * DM + j], acc);
    g_hidden[g * DM + j] = lrelu(acc);
}

__global__ void mlp2_k(const float* __restrict__ Wo2, const float* __restrict__ bo2,
                       float* __restrict__ out) {
    int g = blockIdx.x * blockDim.x + threadIdx.x;
    if (g >= NG) return;
    float acc = bo2[0];
#pragma unroll 8
    for (int k = 0; k < DM; k++) acc = fmaf(g_hidden[g * DM + k], Wo2[k], acc);
    out[g] = acc;
}

// ---------------- host orchestration ---------------------------------------
extern "C" void kernel_launch(void* const* d_in, const int* in_sizes, int n_in,
                              void* d_out, int out_size) {
    const float* x      = (const float*)d_in[0];
    const void*  ei     = d_in[1];
    const void*  batch  = d_in[2];
    const float* W_init = (const float*)d_in[3];
    const float* b_init = (const float*)d_in[4];
    const float* Wl[4]  = {(const float*)d_in[5], (const float*)d_in[7],
                           (const float*)d_in[9], (const float*)d_in[11]};
    const float* bl[4]  = {(const float*)d_in[6], (const float*)d_in[8],
                           (const float*)d_in[10], (const float*)d_in[12]};
    const float* Wo1    = (const float*)d_in[13];
    const float* bo1    = (const float*)d_in[14];
    const float* Wo2    = (const float*)d_in[15];
    const float* bo2    = (const float*)d_in[16];
    float* out = (float*)d_out;

    float* p_agg = nullptr;
    cudaGetSymbolAddress((void**)&p_agg, g_agg);

    const int T = 256;
    const int gridN  = (N_NODES + T - 1) / T;
    const int gridE  = (N_EDGES + T - 1) / T;
    const int gridG  = (N_NODES * 32 + T - 1) / T;   // warp per node
    const int gridMM = (N_NODES + 127) / 128;

    detect_dtype_k<<<1, 256>>>((const int*)ei);
    deg_init_k<<<gridN, T>>>();
    deg_count_k<<<gridE, T>>>(ei);
    dis_k<<<gridN, T>>>();

    // CSR by destination
    scan_part_k<<<NBLK_N, 256>>>();
    scan_top_k<<<1, 256>>>();
    scan_down_k<<<NBLK_N, 256>>>();
    bucket_k<<<gridE, T>>>(ei);

    // pooling offsets
    gcnt_k<<<gridN, T>>>(batch);
    goff_k<<<1, NG>>>();

    // layer 1 (FIN=16)
    gemm_k<FIN0><<<gridMM, 256>>>(x, W_init);
    gather_k<<<gridG, T>>>(b_init);

    // layers 2..5 (FIN=96) — gather output already activated
    for (int l = 0; l < 4; l++) {
        gemm_k<DM><<<gridMM, 256>>>(p_agg, Wl[l]);
        gather_k<<<gridG, T>>>(bl[l]);
    }

    // pooling + MLP head
    pool_seg_k<<<NG, 288>>>();
    mlp1_k<<<NG, DM>>>(Wo1, bo1);
    mlp2_k<<<1, NG>>>(Wo2, bo2, out);
}

// round 7
// speedup vs baseline: 2.8112x; 1.1106x over previous
#include <cuda_runtime.h>
#include <math.h>

#define N_NODES 50000
#define N_EDGES 800000
#define FIN0 16
#define DM 96
#define NG 64
#define NBLK_N 196   // ceil(50000/256)

// ---------------- device scratch (no allocations allowed) ----------------
__device__ float g_h[N_NODES * DM];       // h' = dis[row] * (X @ W)[row]
__device__ float g_agg[N_NODES * DM];     // conv output (leaky-relu applied)
__device__ float g_dis[N_NODES];          // deg^{-1/2}
__device__ int   g_deg[N_NODES];          // includes self-loop
__device__ int   g_rowstart[N_NODES + 1]; // CSR by destination (real edges only)
__device__ int   g_cursor[N_NODES];
__device__ int   g_bsum[NBLK_N];
__device__ int   g_boff[NBLK_N];
__device__ int   g_csr_src[N_EDGES];
__device__ int   g_gcnt[NG];
__device__ int   g_goff[NG + 1];
__device__ int   g_is64;

__device__ __forceinline__ float lrelu(float v) { return v > 0.0f ? v : 0.01f * v; }

__device__ __forceinline__ long long read_idx(const void* p, long long i) {
    if (g_is64) return ((const long long*)p)[i];
    return (long long)((const int*)p)[i];
}

// ---------------- init: dtype detect + deg/gcnt init ------------------------
__global__ void init_k(const int* __restrict__ ei32) {
    int i = blockIdx.x * blockDim.x + threadIdx.x;
    if (blockIdx.x == 0) {
        __shared__ int nz;
        if (threadIdx.x == 0) nz = 0;
        __syncthreads();
        for (int k = threadIdx.x; k < 4096; k += blockDim.x)
            if (ei32[2 * k + 1] != 0) atomicAdd(&nz, 1);
        __syncthreads();
        if (threadIdx.x == 0) g_is64 = (nz == 0) ? 1 : 0;
    }
    if (i < N_NODES) g_deg[i] = 1;  // self-loop
    if (i < NG) g_gcnt[i] = 0;
}

// ---------------- counts: node in-degree + nodes per graph ------------------
__global__ void count_k(const void* __restrict__ ei, const void* __restrict__ batch) {
    int e = blockIdx.x * blockDim.x + threadIdx.x;
    if (e < N_EDGES) atomicAdd(&g_deg[(int)read_idx(ei, (long long)N_EDGES + e)], 1);
    if (e < N_NODES) atomicAdd(&g_gcnt[(int)read_idx(batch, e)], 1);
}

// ---------------- scan level 1 (+ rsqrt) ------------------------------------
__global__ void scanpart_dis_k() {
    __shared__ int sm[256];
    int i = blockIdx.x * 256 + threadIdx.x;
    int d = (i < N_NODES) ? g_deg[i] : 1;
    if (i < N_NODES) g_dis[i] = rsqrtf((float)d);
    sm[threadIdx.x] = (i < N_NODES) ? d - 1 : 0;
    __syncthreads();
    for (int off = 128; off > 0; off >>= 1) {
        if (threadIdx.x < off) sm[threadIdx.x] += sm[threadIdx.x + off];
        __syncthreads();
    }
    if (threadIdx.x == 0) g_bsum[blockIdx.x] = sm[0];
}

// ---------------- scan top level + graph offsets ----------------------------
__global__ void scantop_goff_k() {
    __shared__ int s[256];
    __shared__ int sg[NG];
    int t = threadIdx.x;
    int own = (t < NBLK_N) ? g_bsum[t] : 0;
    s[t] = own;
    if (t < NG) sg[t] = g_gcnt[t];
    __syncthreads();
    for (int off = 1; off < 256; off <<= 1) {
        int v = (t >= off) ? s[t - off] : 0;
        int vg = (t < NG && t >= off) ? sg[t - off] : 0;
        __syncthreads();
        s[t] += v;
        if (t < NG) sg[t] += vg;
        __syncthreads();
    }
    if (t < NBLK_N) g_boff[t] = s[t] - own;
    if (t < NG) g_goff[t + 1] = sg[t];
    if (t == 0) { g_rowstart[N_NODES] = N_EDGES; g_goff[0] = 0; }
}

__global__ void scan_down_k() {
    __shared__ int sm[256];
    int t = threadIdx.x;
    int i = blockIdx.x * 256 + t;
    int v = (i < N_NODES) ? g_deg[i] - 1 : 0;
    sm[t] = v;
    __syncthreads();
    for (int off = 1; off < 256; off <<= 1) {
        int u = (t >= off) ? sm[t - off] : 0;
        __syncthreads();
        sm[t] += u;
        __syncthreads();
    }
    if (i < N_NODES) {
        int rs = g_boff[blockIdx.x] + sm[t] - v;
        g_rowstart[i] = rs;
        g_cursor[i] = rs;
    }
}

__global__ void bucket_k(const void* __restrict__ ei) {
    int e = blockIdx.x * blockDim.x + threadIdx.x;
    if (e >= N_EDGES) return;
    int s = (int)read_idx(ei, e);
    int d = (int)read_idx(ei, (long long)N_EDGES + e);
    int pos = atomicAdd(&g_cursor[d], 1);
    g_csr_src[pos] = s;
}

// ---------------- GEMM: g_h = dis * (X @ W)  (128x96 tile) ------------------
template <int FIN>
__global__ void gemm_k(const float* __restrict__ X, const float* __restrict__ W) {
    __shared__ float Ws[FIN * DM];
    __shared__ float Xs[128 * FIN];
    int node0 = blockIdx.x * 128;
    int nn = N_NODES - node0;
    if (nn > 128) nn = 128;

    for (int i = threadIdx.x; i < FIN * DM; i += 256) Ws[i] = W[i];
    for (int i = threadIdx.x; i < nn * FIN; i += 256) Xs[i] = X[(size_t)node0 * FIN + i];
    __syncthreads();

    int c = (threadIdx.x & 15) * 6;   // column base (0..90)
    int r0 = (threadIdx.x >> 4) * 8;  // row base (0..120)
    float acc[8][6];
#pragma unroll
    for (int r = 0; r < 8; r++)
#pragma unroll
        for (int j = 0; j < 6; j++) acc[r][j] = 0.0f;

#pragma unroll 4
    for (int k = 0; k < FIN; k++) {
        float w0 = Ws[k * DM + c + 0], w1 = Ws[k * DM + c + 1], w2 = Ws[k * DM + c + 2];
        float w3 = Ws[k * DM + c + 3], w4 = Ws[k * DM + c + 4], w5 = Ws[k * DM + c + 5];
#pragma unroll
        for (int r = 0; r < 8; r++) {
            float xv = Xs[(r0 + r) * FIN + k];
            acc[r][0] = fmaf(xv, w0, acc[r][0]);
            acc[r][1] = fmaf(xv, w1, acc[r][1]);
            acc[r][2] = fmaf(xv, w2, acc[r][2]);
            acc[r][3] = fmaf(xv, w3, acc[r][3]);
            acc[r][4] = fmaf(xv, w4, acc[r][4]);
            acc[r][5] = fmaf(xv, w5, acc[r][5]);
        }
    }
#pragma unroll
    for (int r = 0; r < 8; r++) {
        int row = r0 + r;
        if (row < nn) {
            float dn = g_dis[node0 + row];
            float* o = g_h + (size_t)(node0 + row) * DM + c;
#pragma unroll
            for (int j = 0; j < 6; j++) o[j] = acc[r][j] * dn;
        }
    }
}

// ---------------- gather: agg = lrelu(b + dis[d]*(h'[d] + sum h'[src])) ----
__global__ void gather_k(const float* __restrict__ b) {
    int w = (blockIdx.x * blockDim.x + threadIdx.x) >> 5;
    if (w >= N_NODES) return;
    int lane = threadIdx.x & 31;
    int beg = g_rowstart[w], end = g_rowstart[w + 1];
    float dn = g_dis[w];
    const float4* h4 = (const float4*)g_h;
    bool act = lane < 24;
    float4 acc = make_float4(0.f, 0.f, 0.f, 0.f);
    if (act) acc = h4[(size_t)w * 24 + lane];  // self-loop term
    int j = beg;
    for (; j + 1 < end; j += 2) {
        int s0 = __ldg(&g_csr_src[j]);
        int s1 = __ldg(&g_csr_src[j + 1]);
        if (act) {
            float4 v0 = h4[(size_t)s0 * 24 + lane];
            float4 v1 = h4[(size_t)s1 * 24 + lane];
            acc.x += v0.x + v1.x;
            acc.y += v0.y + v1.y;
            acc.z += v0.z + v1.z;
            acc.w += v0.w + v1.w;
        }
    }
    if (j < end) {
        int s = __ldg(&g_csr_src[j]);
        if (act) {
            float4 v = h4[(size_t)s * 24 + lane];
            acc.x += v.x; acc.y += v.y; acc.z += v.z; acc.w += v.w;
        }
    }
    if (act) {
        float4 bb = *(const float4*)(b + lane * 4);
        float4 o;
        o.x = lrelu(fmaf(dn, acc.x, bb.x));
        o.y = lrelu(fmaf(dn, acc.y, bb.y));
        o.z = lrelu(fmaf(dn, acc.z, bb.z));
        o.w = lrelu(fmaf(dn, acc.w, bb.w));
        ((float4*)g_agg)[(size_t)w * 24 + lane] = o;
    }
}

// ---------------- fused tail: pooling + MLP1 + MLP2 -------------------------
__global__ void tail_k(const float* __restrict__ Wo1, const float* __restrict__ bo1,
                       const float* __restrict__ Wo2, const float* __restrict__ bo2,
                       float* __restrict__ out) {
    int g = blockIdx.x;
    int beg = g_goff[g], end = g_goff[g + 1];
    int t = threadIdx.x;                 // 288 threads = 3 x 96
    int f = t % DM, rr = t / DM;
    __shared__ float smx[288], ssm[288];
    __shared__ float pooled[2 * DM];
    __shared__ float hidden[DM];

    float mx = -INFINITY, sm = 0.0f;
    for (int n = beg + rr; n < end; n += 3) {
        float v = g_agg[(size_t)n * DM + f];
        mx = fmaxf(mx, v);
        sm += v;
    }
    smx[t] = mx;
    ssm[t] = sm;
    __syncthreads();
    if (rr == 0) {
        mx = fmaxf(fmaxf(smx[f], smx[f + DM]), smx[f + 2 * DM]);
        sm = ssm[f] + ssm[f + DM] + ssm[f + 2 * DM];
        pooled[f] = mx;
        pooled[DM + f] = sm / fmaxf((float)(end - beg), 1.0f);
    }
    __syncthreads();
    if (t < DM) {
        float acc = bo1[t];
#pragma unroll 8
        for (int k = 0; k < 2 * DM; k++) acc = fmaf(pooled[k], Wo1[k * DM + t], acc);
        hidden[t] = lrelu(acc);
    }
    __syncthreads();
    if (t < 32) {
        float a = 0.0f;
#pragma unroll
        for (int k = t; k < DM; k += 32) a = fmaf(hidden[k], Wo2[k], a);
#pragma unroll
        for (int o = 16; o; o >>= 1) a += __shfl_down_sync(0xffffffff, a, o);
        if (t == 0) out[g] = a + bo2[0];
    }
}

// ---------------- host orchestration ---------------------------------------
extern "C" void kernel_launch(void* const* d_in, const int* in_sizes, int n_in,
                              void* d_out, int out_size) {
    const float* x      = (const float*)d_in[0];
    const void*  ei     = d_in[1];
    const void*  batch  = d_in[2];
    const float* W_init = (const float*)d_in[3];
    const float* b_init = (const float*)d_in[4];
    const float* Wl[4]  = {(const float*)d_in[5], (const float*)d_in[7],
                           (const float*)d_in[9], (const float*)d_in[11]};
    const float* bl[4]  = {(const float*)d_in[6], (const float*)d_in[8],
                           (const float*)d_in[10], (const float*)d_in[12]};
    const float* Wo1    = (const float*)d_in[13];
    const float* bo1    = (const float*)d_in[14];
    const float* Wo2    = (const float*)d_in[15];
    const float* bo2    = (const float*)d_in[16];
    float* out = (float*)d_out;

    float* p_agg = nullptr;
    cudaGetSymbolAddress((void**)&p_agg, g_agg);

    const int T = 256;
    const int gridE  = (N_EDGES + T - 1) / T;
    const int gridG  = (N_NODES * 32 + T - 1) / T;   // warp per node
    const int gridMM = (N_NODES + 127) / 128;

    init_k<<<NBLK_N, T>>>((const int*)ei);
    count_k<<<gridE, T>>>(ei, batch);
    scanpart_dis_k<<<NBLK_N, T>>>();
    scantop_goff_k<<<1, T>>>();
    scan_down_k<<<NBLK_N, T>>>();
    bucket_k<<<gridE, T>>>(ei);

    // layer 1 (FIN=16)
    gemm_k<FIN0><<<gridMM, 256>>>(x, W_init);
    gather_k<<<gridG, T>>>(b_init);

    // layers 2..5 (FIN=96)
    for (int l = 0; l < 4; l++) {
        gemm_k<DM><<<gridMM, 256>>>(p_agg, Wl[l]);
        gather_k<<<gridG, T>>>(bl[l]);
    }

    // fused pooling + MLP head
    tail_k<<<NG, 288>>>(Wo1, bo1, Wo2, bo2, out);
}

// round 9
// speedup vs baseline: 3.0196x; 1.0741x over previous
#include <cuda_runtime.h>
#include <cuda_fp16.h>
#include <math.h>

#define N_NODES 50000
#define N_EDGES 800000
#define FIN0 16
#define DM 96
#define NG 64
#define NBLK_N 196   // ceil(50000/256)

// ---------------- device scratch (no allocations allowed) ----------------
__device__ __align__(16) __half g_h[N_NODES * DM]; // h' = dis[row]*(X@W)[row], fp16
__device__ float g_agg[N_NODES * DM];     // conv output (leaky-relu applied), fp32
__device__ float g_dis[N_NODES];          // deg^{-1/2}
__device__ int   g_deg[N_NODES];          // includes self-loop
__device__ int   g_rowstart[N_NODES + 1]; // CSR by destination (real edges only)
__device__ int   g_cursor[N_NODES];
__device__ int   g_bsum[NBLK_N];
__device__ int   g_boff[NBLK_N];
__device__ int   g_csr_src[N_EDGES];
__device__ int   g_gcnt[NG];
__device__ int   g_goff[NG + 1];
__device__ int   g_is64;

__device__ __forceinline__ float lrelu(float v) { return v > 0.0f ? v : 0.01f * v; }

__device__ __forceinline__ long long read_idx(const void* p, long long i) {
    if (g_is64) return ((const long long*)p)[i];
    return (long long)((const int*)p)[i];
}

// ---------------- init: dtype detect + deg/gcnt init ------------------------
__global__ void init_k(const int* __restrict__ ei32) {
    int i = blockIdx.x * blockDim.x + threadIdx.x;
    if (blockIdx.x == 0) {
        __shared__ int nz;
        if (threadIdx.x == 0) nz = 0;
        __syncthreads();
        for (int k = threadIdx.x; k < 4096; k += blockDim.x)
            if (ei32[2 * k + 1] != 0) atomicAdd(&nz, 1);
        __syncthreads();
        if (threadIdx.x == 0) g_is64 = (nz == 0) ? 1 : 0;
    }
    if (i < N_NODES) g_deg[i] = 1;  // self-loop
    if (i < NG) g_gcnt[i] = 0;
}

// ---------------- counts: node in-degree + nodes per graph ------------------
__global__ void count_k(const void* __restrict__ ei, const void* __restrict__ batch) {
    int e = blockIdx.x * blockDim.x + threadIdx.x;
    if (e < N_EDGES) atomicAdd(&g_deg[(int)read_idx(ei, (long long)N_EDGES + e)], 1);
    if (e < N_NODES) atomicAdd(&g_gcnt[(int)read_idx(batch, e)], 1);
}

// ---------------- scan level 1 (+ rsqrt) ------------------------------------
__global__ void scanpart_dis_k() {
    __shared__ int sm[256];
    int i = blockIdx.x * 256 + threadIdx.x;
    int d = (i < N_NODES) ? g_deg[i] : 1;
    if (i < N_NODES) g_dis[i] = rsqrtf((float)d);
    sm[threadIdx.x] = (i < N_NODES) ? d - 1 : 0;
    __syncthreads();
    for (int off = 128; off > 0; off >>= 1) {
        if (threadIdx.x < off) sm[threadIdx.x] += sm[threadIdx.x + off];
        __syncthreads();
    }
    if (threadIdx.x == 0) g_bsum[blockIdx.x] = sm[0];
}

// ---------------- scan top level + graph offsets ----------------------------
__global__ void scantop_goff_k() {
    __shared__ int s[256];
    __shared__ int sg[NG];
    int t = threadIdx.x;
    int own = (t < NBLK_N) ? g_bsum[t] : 0;
    s[t] = own;
    if (t < NG) sg[t] = g_gcnt[t];
    __syncthreads();
    for (int off = 1; off < 256; off <<= 1) {
        int v = (t >= off) ? s[t - off] : 0;
        int vg = (t < NG && t >= off) ? sg[t - off] : 0;
        __syncthreads();
        s[t] += v;
        if (t < NG) sg[t] += vg;
        __syncthreads();
    }
    if (t < NBLK_N) g_boff[t] = s[t] - own;
    if (t < NG) g_goff[t + 1] = sg[t];
    if (t == 0) { g_rowstart[N_NODES] = N_EDGES; g_goff[0] = 0; }
}

__global__ void scan_down_k() {
    __shared__ int sm[256];
    int t = threadIdx.x;
    int i = blockIdx.x * 256 + t;
    int v = (i < N_NODES) ? g_deg[i] - 1 : 0;
    sm[t] = v;
    __syncthreads();
    for (int off = 1; off < 256; off <<= 1) {
        int u = (t >= off) ? sm[t - off] : 0;
        __syncthreads();
        sm[t] += u;
        __syncthreads();
    }
    if (i < N_NODES) {
        int rs = g_boff[blockIdx.x] + sm[t] - v;
        g_rowstart[i] = rs;
        g_cursor[i] = rs;
    }
}

__global__ void bucket_k(const void* __restrict__ ei) {
    int e = blockIdx.x * blockDim.x + threadIdx.x;
    if (e >= N_EDGES) return;
    int s = (int)read_idx(ei, e);
    int d = (int)read_idx(ei, (long long)N_EDGES + e);
    int pos = atomicAdd(&g_cursor[d], 1);
    g_csr_src[pos] = s;
}

// ---------------- GEMM: g_h = half(dis * (X @ W))  (128x96 tile) ------------
template <int FIN>
__global__ void gemm_k(const float* __restrict__ X, const float* __restrict__ W) {
    __shared__ float Ws[FIN * DM];
    __shared__ float Xs[128 * FIN];
    int node0 = blockIdx.x * 128;
    int nn = N_NODES - node0;
    if (nn > 128) nn = 128;

    for (int i = threadIdx.x; i < FIN * DM; i += 256) Ws[i] = W[i];
    for (int i = threadIdx.x; i < nn * FIN; i += 256) Xs[i] = X[(size_t)node0 * FIN + i];
    __syncthreads();

    int c = (threadIdx.x & 15) * 6;   // column base (0..90), even
    int r0 = (threadIdx.x >> 4) * 8;  // row base (0..120)
    float acc[8][6];
#pragma unroll
    for (int r = 0; r < 8; r++)
#pragma unroll
        for (int j = 0; j < 6; j++) acc[r][j] = 0.0f;

#pragma unroll 4
    for (int k = 0; k < FIN; k++) {
        float w0 = Ws[k * DM + c + 0], w1 = Ws[k * DM + c + 1], w2 = Ws[k * DM + c + 2];
        float w3 = Ws[k * DM + c + 3], w4 = Ws[k * DM + c + 4], w5 = Ws[k * DM + c + 5];
#pragma unroll
        for (int r = 0; r < 8; r++) {
            float xv = Xs[(r0 + r) * FIN + k];
            acc[r][0] = fmaf(xv, w0, acc[r][0]);
            acc[r][1] = fmaf(xv, w1, acc[r][1]);
            acc[r][2] = fmaf(xv, w2, acc[r][2]);
            acc[r][3] = fmaf(xv, w3, acc[r][3]);
            acc[r][4] = fmaf(xv, w4, acc[r][4]);
            acc[r][5] = fmaf(xv, w5, acc[r][5]);
        }
    }
#pragma unroll
    for (int r = 0; r < 8; r++) {
        int row = r0 + r;
        if (row < nn) {
            float dn = g_dis[node0 + row];
            __half2* o = (__half2*)(g_h + (size_t)(node0 + row) * DM + c);
            o[0] = __floats2half2_rn(acc[r][0] * dn, acc[r][1] * dn);
            o[1] = __floats2half2_rn(acc[r][2] * dn, acc[r][3] * dn);
            o[2] = __floats2half2_rn(acc[r][4] * dn, acc[r][5] * dn);
        }
    }
}

// ---------------- gather: agg = lrelu(b + dis[d]*(h'[d] + sum h'[src])) ----
// fp16 rows (192B). 24 active lanes, each owns 4 features = one 8B load/edge.
__global__ void gather_k(const float* __restrict__ b) {
    int w = (blockIdx.x * blockDim.x + threadIdx.x) >> 5;
    if (w >= N_NODES) return;
    int lane = threadIdx.x & 31;
    bool act = lane < 24;
    int beg = g_rowstart[w], end = g_rowstart[w + 1];
    float dn = g_dis[w];
    const float2* h2 = (const float2*)g_h;  // 4 halves per float2; 24 per row
    float4 acc = make_float4(0.f, 0.f, 0.f, 0.f);

#define ACC_ROW(sidx) do {                                             \
        float2 raw = __ldg(&h2[(size_t)(sidx) * 24 + lane]);           \
        __half2 p0 = *reinterpret_cast<const __half2*>(&raw.x);        \
        __half2 p1 = *reinterpret_cast<const __half2*>(&raw.y);        \
        float2 f0 = __half22float2(p0), f1 = __half22float2(p1);       \
        acc.x += f0.x; acc.y += f0.y; acc.z += f1.x; acc.w += f1.y;    \
    } while (0)

    if (act) ACC_ROW(w);  // self-loop term
    int j = beg;
    for (; j + 3 < end; j += 4) {
        int s0 = __ldg(&g_csr_src[j]);
        int s1 = __ldg(&g_csr_src[j + 1]);
        int s2 = __ldg(&g_csr_src[j + 2]);
        int s3 = __ldg(&g_csr_src[j + 3]);
        if (act) { ACC_ROW(s0); ACC_ROW(s1); ACC_ROW(s2); ACC_ROW(s3); }
    }
    for (; j < end; j++) {
        int s = __ldg(&g_csr_src[j]);
        if (act) ACC_ROW(s);
    }
#undef ACC_ROW

    if (act) {
        float4 bb = *(const float4*)(b + lane * 4);
        float4 o;
        o.x = lrelu(fmaf(dn, acc.x, bb.x));
        o.y = lrelu(fmaf(dn, acc.y, bb.y));
        o.z = lrelu(fmaf(dn, acc.z, bb.z));
        o.w = lrelu(fmaf(dn, acc.w, bb.w));
        ((float4*)g_agg)[(size_t)w * 24 + lane] = o;
    }
}

// ---------------- fused tail: pooling + MLP1 + MLP2 -------------------------
__global__ void tail_k(const float* __restrict__ Wo1, const float* __restrict__ bo1,
                       const float* __restrict__ Wo2, const float* __restrict__ bo2,
                       float* __restrict__ out) {
    int g = blockIdx.x;
    int beg = g_goff[g], end = g_goff[g + 1];
    int t = threadIdx.x;                 // 288 threads = 3 x 96
    int f = t % DM, rr = t / DM;
    __shared__ float smx[288], ssm[288];
    __shared__ float pooled[2 * DM];
    __shared__ float hidden[DM];

    float mx = -INFINITY, sm = 0.0f;
    for (int n = beg + rr; n < end; n += 3) {
        float v = g_agg[(size_t)n * DM + f];
        mx = fmaxf(mx, v);
        sm += v;
    }
    smx[t] = mx;
    ssm[t] = sm;
    __syncthreads();
    if (rr == 0) {
        mx = fmaxf(fmaxf(smx[f], smx[f + DM]), smx[f + 2 * DM]);
        sm = ssm[f] + ssm[f + DM] + ssm[f + 2 * DM];
        pooled[f] = mx;
        pooled[DM + f] = sm / fmaxf((float)(end - beg), 1.0f);
    }
    __syncthreads();
    if (t < DM) {
        float acc = bo1[t];
#pragma unroll 8
        for (int k = 0; k < 2 * DM; k++) acc = fmaf(pooled[k], Wo1[k * DM + t], acc);
        hidden[t] = lrelu(acc);
    }
    __syncthreads();
    if (t < 32) {
        float a = 0.0f;
#pragma unroll
        for (int k = t; k < DM; k += 32) a = fmaf(hidden[k], Wo2[k], a);
#pragma unroll
        for (int o = 16; o; o >>= 1) a += __shfl_down_sync(0xffffffff, a, o);
        if (t == 0) out[g] = a + bo2[0];
    }
}

// ---------------- host orchestration ---------------------------------------
extern "C" void kernel_launch(void* const* d_in, const int* in_sizes, int n_in,
                              void* d_out, int out_size) {
    const float* x      = (const float*)d_in[0];
    const void*  ei     = d_in[1];
    const void*  batch  = d_in[2];
    const float* W_init = (const float*)d_in[3];
    const float* b_init = (const float*)d_in[4];
    const float* Wl[4]  = {(const float*)d_in[5], (const float*)d_in[7],
                           (const float*)d_in[9], (const float*)d_in[11]};
    const float* bl[4]  = {(const float*)d_in[6], (const float*)d_in[8],
                           (const float*)d_in[10], (const float*)d_in[12]};
    const float* Wo1    = (const float*)d_in[13];
    const float* bo1    = (const float*)d_in[14];
    const float* Wo2    = (const float*)d_in[15];
    const float* bo2    = (const float*)d_in[16];
    float* out = (float*)d_out;

    float* p_agg = nullptr;
    cudaGetSymbolAddress((void**)&p_agg, g_agg);

    const int T = 256;
    const int gridE  = (N_EDGES + T - 1) / T;
    const int gridG  = (N_NODES * 32 + T - 1) / T;   // warp per node
    const int gridMM = (N_NODES + 127) / 128;

    init_k<<<NBLK_N, T>>>((const int*)ei);
    count_k<<<gridE, T>>>(ei, batch);
    scanpart_dis_k<<<NBLK_N, T>>>();
    scantop_goff_k<<<1, T>>>();
    scan_down_k<<<NBLK_N, T>>>();
    bucket_k<<<gridE, T>>>(ei);

    // layer 1 (FIN=16)
    gemm_k<FIN0><<<gridMM, 256>>>(x, W_init);
    gather_k<<<gridG, T>>>(b_init);

    // layers 2..5 (FIN=96)
    for (int l = 0; l < 4; l++) {
        gemm_k<DM><<<gridMM, 256>>>(p_agg, Wl[l]);
        gather_k<<<gridG, T>>>(bl[l]);
    }

    // fused pooling + MLP head
    tail_k<<<NG, 288>>>(Wo1, bo1, Wo2, bo2, out);
}

// round 10
// speedup vs baseline: 3.1104x; 1.0301x over previous
#include <cuda_runtime.h>
#include <cuda_fp16.h>
#include <math.h>

#define N_NODES 50000
#define N_EDGES 800000
#define FIN0 16
#define DM 96
#define NG 64
#define NBLK_N 196   // ceil(50000/256)

// ---------------- device scratch (no allocations allowed) ----------------
__device__ __align__(16) __half g_h[N_NODES * DM];   // h' = dis*(X@W), fp16
__device__ __align__(16) __half g_x16[N_NODES * FIN0]; // x' = dis*x, fp16
__device__ float g_aggx[N_NODES * FIN0]; // layer-1 pre-GEMM aggregate (fp32)
__device__ float g_agg[N_NODES * DM];    // conv output (leaky-relu applied)
__device__ float g_dis[N_NODES];         // deg^{-1/2}
__device__ int   g_deg[N_NODES];         // includes self-loop
__device__ int   g_rowstart[N_NODES + 1];
__device__ int   g_cursor[N_NODES];
__device__ int   g_bsum[NBLK_N];
__device__ int   g_boff[NBLK_N];
__device__ int   g_csr_src[N_EDGES];
__device__ int   g_gcnt[NG];
__device__ int   g_goff[NG + 1];
__device__ int   g_is64;

__device__ __forceinline__ float lrelu(float v) { return v > 0.0f ? v : 0.01f * v; }

__device__ __forceinline__ long long read_idx(const void* p, long long i) {
    if (g_is64) return ((const long long*)p)[i];
    return (long long)((const int*)p)[i];
}

// ---------------- init: dtype detect + deg/gcnt init ------------------------
__global__ void init_k(const int* __restrict__ ei32) {
    int i = blockIdx.x * blockDim.x + threadIdx.x;
    if (blockIdx.x == 0) {
        __shared__ int nz;
        if (threadIdx.x == 0) nz = 0;
        __syncthreads();
        for (int k = threadIdx.x; k < 4096; k += blockDim.x)
            if (ei32[2 * k + 1] != 0) atomicAdd(&nz, 1);
        __syncthreads();
        if (threadIdx.x == 0) g_is64 = (nz == 0) ? 1 : 0;
    }
    if (i < N_NODES) g_deg[i] = 1;  // self-loop
    if (i < NG) g_gcnt[i] = 0;
}

// ---------------- counts ----------------------------------------------------
__global__ void count_k(const void* __restrict__ ei, const void* __restrict__ batch) {
    int e = blockIdx.x * blockDim.x + threadIdx.x;
    if (e < N_EDGES) atomicAdd(&g_deg[(int)read_idx(ei, (long long)N_EDGES + e)], 1);
    if (e < N_NODES) atomicAdd(&g_gcnt[(int)read_idx(batch, e)], 1);
}

// ---------------- scan level 1 (+ rsqrt + x scale) ---------------------------
__global__ void scanpart_dis_k(const float* __restrict__ x) {
    __shared__ int sm[256];
    int i = blockIdx.x * 256 + threadIdx.x;
    float dn = 1.0f;
    int d = (i < N_NODES) ? g_deg[i] : 1;
    if (i < N_NODES) {
        dn = rsqrtf((float)d);
        g_dis[i] = dn;
        // x' = dis * x (16 features, fp16)
        const float* xr = x + (size_t)i * FIN0;
        __half2* o = (__half2*)(g_x16 + (size_t)i * FIN0);
#pragma unroll
        for (int f = 0; f < FIN0 / 2; f++)
            o[f] = __floats2half2_rn(xr[2 * f] * dn, xr[2 * f + 1] * dn);
    }
    sm[threadIdx.x] = (i < N_NODES) ? d - 1 : 0;
    __syncthreads();
    for (int off = 128; off > 0; off >>= 1) {
        if (threadIdx.x < off) sm[threadIdx.x] += sm[threadIdx.x + off];
        __syncthreads();
    }
    if (threadIdx.x == 0) g_bsum[blockIdx.x] = sm[0];
}

// ---------------- scan top level + graph offsets ----------------------------
__global__ void scantop_goff_k() {
    __shared__ int s[256];
    __shared__ int sg[NG];
    int t = threadIdx.x;
    int own = (t < NBLK_N) ? g_bsum[t] : 0;
    s[t] = own;
    if (t < NG) sg[t] = g_gcnt[t];
    __syncthreads();
    for (int off = 1; off < 256; off <<= 1) {
        int v = (t >= off) ? s[t - off] : 0;
        int vg = (t < NG && t >= off) ? sg[t - off] : 0;
        __syncthreads();
        s[t] += v;
        if (t < NG) sg[t] += vg;
        __syncthreads();
    }
    if (t < NBLK_N) g_boff[t] = s[t] - own;
    if (t < NG) g_goff[t + 1] = sg[t];
    if (t == 0) { g_rowstart[N_NODES] = N_EDGES; g_goff[0] = 0; }
}

__global__ void scan_down_k() {
    __shared__ int sm[256];
    int t = threadIdx.x;
    int i = blockIdx.x * 256 + t;
    int v = (i < N_NODES) ? g_deg[i] - 1 : 0;
    sm[t] = v;
    __syncthreads();
    for (int off = 1; off < 256; off <<= 1) {
        int u = (t >= off) ? sm[t - off] : 0;
        __syncthreads();
        sm[t] += u;
        __syncthreads();
    }
    if (i < N_NODES) {
        int rs = g_boff[blockIdx.x] + sm[t] - v;
        g_rowstart[i] = rs;
        g_cursor[i] = rs;
    }
}

__global__ void bucket_k(const void* __restrict__ ei) {
    int e = blockIdx.x * blockDim.x + threadIdx.x;
    if (e >= N_EDGES) return;
    int s = (int)read_idx(ei, e);
    int d = (int)read_idx(ei, (long long)N_EDGES + e);
    int pos = atomicAdd(&g_cursor[d], 1);
    g_csr_src[pos] = s;
}

// ---------------- layer-1 gather in 16-dim input space ----------------------
// aggx[d] = dis[d] * (x'[d] + sum x'[src]);  8 lanes per node, half2 per lane.
__global__ void gather16_k() {
    int gtid = blockIdx.x * blockDim.x + threadIdx.x;
    int node = gtid >> 3;
    if (node >= N_NODES) return;
    int sub = gtid & 7;
    const __half2* x2 = (const __half2*)g_x16;  // 8 half2 per row
    int beg = g_rowstart[node], end = g_rowstart[node + 1];
    float dn = g_dis[node];
    float2 acc = __half22float2(__ldg(&x2[(size_t)node * 8 + sub]));  // self
    int j = beg;
    for (; j + 3 < end; j += 4) {
        int s0 = __ldg(&g_csr_src[j]);
        int s1 = __ldg(&g_csr_src[j + 1]);
        int s2 = __ldg(&g_csr_src[j + 2]);
        int s3 = __ldg(&g_csr_src[j + 3]);
        float2 v0 = __half22float2(__ldg(&x2[(size_t)s0 * 8 + sub]));
        float2 v1 = __half22float2(__ldg(&x2[(size_t)s1 * 8 + sub]));
        float2 v2 = __half22float2(__ldg(&x2[(size_t)s2 * 8 + sub]));
        float2 v3 = __half22float2(__ldg(&x2[(size_t)s3 * 8 + sub]));
        acc.x += (v0.x + v1.x) + (v2.x + v3.x);
        acc.y += (v0.y + v1.y) + (v2.y + v3.y);
    }
    for (; j < end; j++) {
        int s = __ldg(&g_csr_src[j]);
        float2 v = __half22float2(__ldg(&x2[(size_t)s * 8 + sub]));
        acc.x += v.x; acc.y += v.y;
    }
    ((float2*)g_aggx)[(size_t)node * 8 + sub] = make_float2(acc.x * dn, acc.y * dn);
}

// ---------------- GEMM (128x96 tile, 8x6 regs/thread) -----------------------
// EPI 0: write h' = dis*(X@W) as fp16 (for gather)
// EPI 1: write lrelu(X@W + b) as fp32 to g_agg (layer-1 output)
template <int FIN, int EPI>
__global__ void gemm_k(const float* __restrict__ X, const float* __restrict__ W,
                       const float* __restrict__ b) {
    __shared__ float Ws[FIN * DM];
    __shared__ float Xs[128 * FIN];
    int node0 = blockIdx.x * 128;
    int nn = N_NODES - node0;
    if (nn > 128) nn = 128;

    for (int i = threadIdx.x; i < FIN * DM; i += 256) Ws[i] = W[i];
    for (int i = threadIdx.x; i < nn * FIN; i += 256) Xs[i] = X[(size_t)node0 * FIN + i];
    __syncthreads();

    int c = (threadIdx.x & 15) * 6;   // column base (0..90)
    int r0 = (threadIdx.x >> 4) * 8;  // row base (0..120)
    float acc[8][6];
#pragma unroll
    for (int r = 0; r < 8; r++)
#pragma unroll
        for (int j = 0; j < 6; j++) acc[r][j] = 0.0f;

#pragma unroll 4
    for (int k = 0; k < FIN; k++) {
        float w0 = Ws[k * DM + c + 0], w1 = Ws[k * DM + c + 1], w2 = Ws[k * DM + c + 2];
        float w3 = Ws[k * DM + c + 3], w4 = Ws[k * DM + c + 4], w5 = Ws[k * DM + c + 5];
#pragma unroll
        for (int r = 0; r < 8; r++) {
            float xv = Xs[(r0 + r) * FIN + k];
            acc[r][0] = fmaf(xv, w0, acc[r][0]);
            acc[r][1] = fmaf(xv, w1, acc[r][1]);
            acc[r][2] = fmaf(xv, w2, acc[r][2]);
            acc[r][3] = fmaf(xv, w3, acc[r][3]);
            acc[r][4] = fmaf(xv, w4, acc[r][4]);
            acc[r][5] = fmaf(xv, w5, acc[r][5]);
        }
    }
#pragma unroll
    for (int r = 0; r < 8; r++) {
        int row = r0 + r;
        if (row < nn) {
            if (EPI == 0) {
                float dn = g_dis[node0 + row];
                __half2* o = (__half2*)(g_h + (size_t)(node0 + row) * DM + c);
                o[0] = __floats2half2_rn(acc[r][0] * dn, acc[r][1] * dn);
                o[1] = __floats2half2_rn(acc[r][2] * dn, acc[r][3] * dn);
                o[2] = __floats2half2_rn(acc[r][4] * dn, acc[r][5] * dn);
            } else {
                float* o = g_agg + (size_t)(node0 + row) * DM + c;
#pragma unroll
                for (int j = 0; j < 6; j++) o[j] = lrelu(acc[r][j] + b[c + j]);
            }
        }
    }
}

// ---------------- gather: agg = lrelu(b + dis[d]*(h'[d] + sum h'[src])) ----
// fp16 rows (192B). 24 active lanes, float2 (4 features) per lane, unroll 8.
__global__ void gather_k(const float* __restrict__ b) {
    int w = (blockIdx.x * blockDim.x + threadIdx.x) >> 5;
    if (w >= N_NODES) return;
    int lane = threadIdx.x & 31;
    bool act = lane < 24;
    int beg = g_rowstart[w], end = g_rowstart[w + 1];
    float dn = g_dis[w];
    const float2* h2 = (const float2*)g_h;  // 24 float2 per row
    float4 acc = make_float4(0.f, 0.f, 0.f, 0.f);

#define ACC_ROW(raw) do {                                              \
        __half2 p0 = *reinterpret_cast<const __half2*>(&(raw).x);      \
        __half2 p1 = *reinterpret_cast<const __half2*>(&(raw).y);      \
        float2 f0 = __half22float2(p0), f1 = __half22float2(p1);       \
        acc.x += f0.x; acc.y += f0.y; acc.z += f1.x; acc.w += f1.y;    \
    } while (0)

    if (act) { float2 rw = __ldg(&h2[(size_t)w * 24 + lane]); ACC_ROW(rw); }
    int j = beg;
    for (; j + 7 < end; j += 8) {
        int s[8];
#pragma unroll
        for (int u = 0; u < 8; u++) s[u] = __ldg(&g_csr_src[j + u]);
        if (act) {
            float2 r[8];
#pragma unroll
            for (int u = 0; u < 8; u++) r[u] = __ldg(&h2[(size_t)s[u] * 24 + lane]);
#pragma unroll
            for (int u = 0; u < 8; u++) ACC_ROW(r[u]);
        }
    }
    for (; j + 1 < end; j += 2) {
        int s0 = __ldg(&g_csr_src[j]);
        int s1 = __ldg(&g_csr_src[j + 1]);
        if (act) {
            float2 r0 = __ldg(&h2[(size_t)s0 * 24 + lane]);
            float2 r1 = __ldg(&h2[(size_t)s1 * 24 + lane]);
            ACC_ROW(r0); ACC_ROW(r1);
        }
    }
    if (j < end) {
        int s = __ldg(&g_csr_src[j]);
        if (act) { float2 r = __ldg(&h2[(size_t)s * 24 + lane]); ACC_ROW(r); }
    }
#undef ACC_ROW

    if (act) {
        float4 bb = *(const float4*)(b + lane * 4);
        float4 o;
        o.x = lrelu(fmaf(dn, acc.x, bb.x));
        o.y = lrelu(fmaf(dn, acc.y, bb.y));
        o.z = lrelu(fmaf(dn, acc.z, bb.z));
        o.w = lrelu(fmaf(dn, acc.w, bb.w));
        ((float4*)g_agg)[(size_t)w * 24 + lane] = o;
    }
}

// ---------------- fused tail: pooling + MLP1 + MLP2 -------------------------
__global__ void tail_k(const float* __restrict__ Wo1, const float* __restrict__ bo1,
                       const float* __restrict__ Wo2, const float* __restrict__ bo2,
                       float* __restrict__ out) {
    int g = blockIdx.x;
    int beg = g_goff[g], end = g_goff[g + 1];
    int t = threadIdx.x;                 // 288 threads = 3 x 96
    int f = t % DM, rr = t / DM;
    __shared__ float smx[288], ssm[288];
    __shared__ float pooled[2 * DM];
    __shared__ float hidden[DM];

    float mx = -INFINITY, sm = 0.0f;
    for (int n = beg + rr; n < end; n += 3) {
        float v = g_agg[(size_t)n * DM + f];
        mx = fmaxf(mx, v);
        sm += v;
    }
    smx[t] = mx;
    ssm[t] = sm;
    __syncthreads();
    if (rr == 0) {
        mx = fmaxf(fmaxf(smx[f], smx[f + DM]), smx[f + 2 * DM]);
        sm = ssm[f] + ssm[f + DM] + ssm[f + 2 * DM];
        pooled[f] = mx;
        pooled[DM + f] = sm / fmaxf((float)(end - beg), 1.0f);
    }
    __syncthreads();
    if (t < DM) {
        float acc = bo1[t];
#pragma unroll 8
        for (int k = 0; k < 2 * DM; k++) acc = fmaf(pooled[k], Wo1[k * DM + t], acc);
        hidden[t] = lrelu(acc);
    }
    __syncthreads();
    if (t < 32) {
        float a = 0.0f;
#pragma unroll
        for (int k = t; k < DM; k += 32) a = fmaf(hidden[k], Wo2[k], a);
#pragma unroll
        for (int o = 16; o; o >>= 1) a += __shfl_down_sync(0xffffffff, a, o);
        if (t == 0) out[g] = a + bo2[0];
    }
}

// ---------------- host orchestration ---------------------------------------
extern "C" void kernel_launch(void* const* d_in, const int* in_sizes, int n_in,
                              void* d_out, int out_size) {
    const float* x      = (const float*)d_in[0];
    const void*  ei     = d_in[1];
    const void*  batch  = d_in[2];
    const float* W_init = (const float*)d_in[3];
    const float* b_init = (const float*)d_in[4];
    const float* Wl[4]  = {(const float*)d_in[5], (const float*)d_in[7],
                           (const float*)d_in[9], (const float*)d_in[11]};
    const float* bl[4]  = {(const float*)d_in[6], (const float*)d_in[8],
                           (const float*)d_in[10], (const float*)d_in[12]};
    const float* Wo1    = (const float*)d_in[13];
    const float* bo1    = (const float*)d_in[14];
    const float* Wo2    = (const float*)d_in[15];
    const float* bo2    = (const float*)d_in[16];
    float* out = (float*)d_out;

    float* p_agg = nullptr;
    float* p_aggx = nullptr;
    cudaGetSymbolAddress((void**)&p_agg, g_agg);
    cudaGetSymbolAddress((void**)&p_aggx, g_aggx);

    const int T = 256;
    const int gridE   = (N_EDGES + T - 1) / T;
    const int gridG   = (N_NODES * 32 + T - 1) / T;   // warp per node
    const int gridG16 = (N_NODES * 8 + T - 1) / T;    // 8 lanes per node
    const int gridMM  = (N_NODES + 127) / 128;

    init_k<<<NBLK_N, T>>>((const int*)ei);
    count_k<<<gridE, T>>>(ei, batch);
    scanpart_dis_k<<<NBLK_N, T>>>(x);
    scantop_goff_k<<<1, T>>>();
    scan_down_k<<<NBLK_N, T>>>();
    bucket_k<<<gridE, T>>>(ei);

    // layer 1: aggregate in 16-dim input space, then GEMM with lrelu(+b)
    gather16_k<<<gridG16, T>>>();
    gemm_k<FIN0, 1><<<gridMM, 256>>>(p_aggx, W_init, b_init);

    // layers 2..5 (FIN=96)
    for (int l = 0; l < 4; l++) {
        gemm_k<DM, 0><<<gridMM, 256>>>(p_agg, Wl[l], nullptr);
        gather_k<<<gridG, T>>>(bl[l]);
    }

    // fused pooling + MLP head
    tail_k<<<NG, 288>>>(Wo1, bo1, Wo2, bo2, out);
}

// round 11
// speedup vs baseline: 3.8107x; 1.2251x over previous
#include <cuda_runtime.h>
#include <cuda_fp16.h>
#include <mma.h>
#include <math.h>

using namespace nvcuda;

#define N_NODES 50000
#define N_PAD   50048   // multiple of 128 for wmma tiles
#define N_EDGES 800000
#define FIN0 16
#define DM 96
#define NG 64
#define NBLK_N 196   // ceil(50000/256)

// ---------------- device scratch (no allocations allowed) ----------------
__device__ __align__(16) __half g_h[N_PAD * DM];      // h' = dis*(X@W), fp16
__device__ __align__(16) __half g_x16[N_NODES * FIN0];// x' = dis*x, fp16
__device__ __align__(16) __half g_aggx16[N_PAD * FIN0]; // layer-1 aggregate, fp16
__device__ __align__(16) __half g_agg16[N_PAD * DM];  // conv output (lrelu), fp16
__device__ float g_dis[N_PAD];           // deg^{-1/2}; pad rows = 0
__device__ int   g_deg[N_NODES];         // includes self-loop
__device__ int   g_rowstart[N_NODES + 1];
__device__ int   g_cursor[N_NODES];
__device__ int   g_bsum[NBLK_N];
__device__ int   g_boff[NBLK_N];
__device__ int   g_csr_src[N_EDGES];
__device__ int   g_gcnt[NG];
__device__ int   g_goff[NG + 1];
__device__ int   g_is64;

__device__ __forceinline__ float lrelu(float v) { return v > 0.0f ? v : 0.01f * v; }

__device__ __forceinline__ long long read_idx(const void* p, long long i) {
    if (g_is64) return ((const long long*)p)[i];
    return (long long)((const int*)p)[i];
}

// ---------------- init: dtype detect + deg/gcnt init ------------------------
__global__ void init_k(const int* __restrict__ ei32) {
    int i = blockIdx.x * blockDim.x + threadIdx.x;
    if (blockIdx.x == 0) {
        __shared__ int nz;
        if (threadIdx.x == 0) nz = 0;
        __syncthreads();
        for (int k = threadIdx.x; k < 4096; k += blockDim.x)
            if (ei32[2 * k + 1] != 0) atomicAdd(&nz, 1);
        __syncthreads();
        if (threadIdx.x == 0) g_is64 = (nz == 0) ? 1 : 0;
    }
    if (i < N_NODES) g_deg[i] = 1;  // self-loop
    else if (i < N_PAD) g_dis[i] = 0.0f;  // zero pad norm -> zero pad h rows
    if (i < NG) g_gcnt[i] = 0;
}

// ---------------- counts ----------------------------------------------------
__global__ void count_k(const void* __restrict__ ei, const void* __restrict__ batch) {
    int e = blockIdx.x * blockDim.x + threadIdx.x;
    if (e < N_EDGES) atomicAdd(&g_deg[(int)read_idx(ei, (long long)N_EDGES + e)], 1);
    if (e < N_NODES) atomicAdd(&g_gcnt[(int)read_idx(batch, e)], 1);
}

// ---------------- scan level 1 (+ rsqrt + x scale) ---------------------------
__global__ void scanpart_dis_k(const float* __restrict__ x) {
    __shared__ int sm[256];
    int i = blockIdx.x * 256 + threadIdx.x;
    int d = (i < N_NODES) ? g_deg[i] : 1;
    if (i < N_NODES) {
        float dn = rsqrtf((float)d);
        g_dis[i] = dn;
        const float* xr = x + (size_t)i * FIN0;
        __half2* o = (__half2*)(g_x16 + (size_t)i * FIN0);
#pragma unroll
        for (int f = 0; f < FIN0 / 2; f++)
            o[f] = __floats2half2_rn(xr[2 * f] * dn, xr[2 * f + 1] * dn);
    }
    sm[threadIdx.x] = (i < N_NODES) ? d - 1 : 0;
    __syncthreads();
    for (int off = 128; off > 0; off >>= 1) {
        if (threadIdx.x < off) sm[threadIdx.x] += sm[threadIdx.x + off];
        __syncthreads();
    }
    if (threadIdx.x == 0) g_bsum[blockIdx.x] = sm[0];
}

// ---------------- scan top level + graph offsets ----------------------------
__global__ void scantop_goff_k() {
    __shared__ int s[256];
    __shared__ int sg[NG];
    int t = threadIdx.x;
    int own = (t < NBLK_N) ? g_bsum[t] : 0;
    s[t] = own;
    if (t < NG) sg[t] = g_gcnt[t];
    __syncthreads();
    for (int off = 1; off < 256; off <<= 1) {
        int v = (t >= off) ? s[t - off] : 0;
        int vg = (t < NG && t >= off) ? sg[t - off] : 0;
        __syncthreads();
        s[t] += v;
        if (t < NG) sg[t] += vg;
        __syncthreads();
    }
    if (t < NBLK_N) g_boff[t] = s[t] - own;
    if (t < NG) g_goff[t + 1] = sg[t];
    if (t == 0) { g_rowstart[N_NODES] = N_EDGES; g_goff[0] = 0; }
}

__global__ void scan_down_k() {
    __shared__ int sm[256];
    int t = threadIdx.x;
    int i = blockIdx.x * 256 + t;
    int v = (i < N_NODES) ? g_deg[i] - 1 : 0;
    sm[t] = v;
    __syncthreads();
    for (int off = 1; off < 256; off <<= 1) {
        int u = (t >= off) ? sm[t - off] : 0;
        __syncthreads();
        sm[t] += u;
        __syncthreads();
    }
    if (i < N_NODES) {
        int rs = g_boff[blockIdx.x] + sm[t] - v;
        g_rowstart[i] = rs;
        g_cursor[i] = rs;
    }
}

__global__ void bucket_k(const void* __restrict__ ei) {
    int e = blockIdx.x * blockDim.x + threadIdx.x;
    if (e >= N_EDGES) return;
    int s = (int)read_idx(ei, e);
    int d = (int)read_idx(ei, (long long)N_EDGES + e);
    int pos = atomicAdd(&g_cursor[d], 1);
    g_csr_src[pos] = s;
}

// ---------------- layer-1 gather in 16-dim input space ----------------------
// aggx16[d] = half(dis[d] * (x'[d] + sum x'[src])); 8 lanes per node.
__global__ void gather16_k() {
    int gtid = blockIdx.x * blockDim.x + threadIdx.x;
    int node = gtid >> 3;
    if (node >= N_NODES) return;
    int sub = gtid & 7;
    const __half2* x2 = (const __half2*)g_x16;  // 8 half2 per row
    int beg = g_rowstart[node], end = g_rowstart[node + 1];
    float dn = g_dis[node];
    float2 acc = __half22float2(__ldg(&x2[(size_t)node * 8 + sub]));  // self
    int j = beg;
    for (; j + 3 < end; j += 4) {
        int s0 = __ldg(&g_csr_src[j]);
        int s1 = __ldg(&g_csr_src[j + 1]);
        int s2 = __ldg(&g_csr_src[j + 2]);
        int s3 = __ldg(&g_csr_src[j + 3]);
        float2 v0 = __half22float2(__ldg(&x2[(size_t)s0 * 8 + sub]));
        float2 v1 = __half22float2(__ldg(&x2[(size_t)s1 * 8 + sub]));
        float2 v2 = __half22float2(__ldg(&x2[(size_t)s2 * 8 + sub]));
        float2 v3 = __half22float2(__ldg(&x2[(size_t)s3 * 8 + sub]));
        acc.x += (v0.x + v1.x) + (v2.x + v3.x);
        acc.y += (v0.y + v1.y) + (v2.y + v3.y);
    }
    for (; j < end; j++) {
        int s = __ldg(&g_csr_src[j]);
        float2 v = __half22float2(__ldg(&x2[(size_t)s * 8 + sub]));
        acc.x += v.x; acc.y += v.y;
    }
    ((__half2*)g_aggx16)[(size_t)node * 8 + sub] = __floats2half2_rn(acc.x * dn, acc.y * dn);
}

// ---------------- wmma GEMM: out = A[fp16] @ W, 128x96 tile -----------------
// EPI 0: g_h = half(dis * (A@W))     (for gather)
// EPI 1: g_agg16 = half(lrelu(A@W + b))  (layer-1 output)
template <int KDIM, int EPI>
__global__ void gemm_wmma_k(const __half* __restrict__ A, const float* __restrict__ Wf,
                            const float* __restrict__ b) {
    __shared__ __half Bs[KDIM * DM];
    __shared__ float bias_s[DM];
    __shared__ float stage[8][16 * 48];   // half-width staging per warp (24KB)
    int tid = threadIdx.x;
    for (int i = tid; i < KDIM * DM; i += 256) Bs[i] = __float2half(Wf[i]);
    if (EPI == 1) { if (tid < DM) bias_s[tid] = b[tid]; }
    __syncthreads();

    int warp = tid >> 5;
    int lane = tid & 31;
    int row0 = blockIdx.x * 128 + warp * 16;

    wmma::fragment<wmma::accumulator, 16, 16, 16, float> c[6];
#pragma unroll
    for (int j = 0; j < 6; j++) wmma::fill_fragment(c[j], 0.0f);
#pragma unroll
    for (int k = 0; k < KDIM / 16; k++) {
        wmma::fragment<wmma::matrix_a, 16, 16, 16, __half, wmma::row_major> a;
        wmma::load_matrix_sync(a, A + (size_t)row0 * KDIM + k * 16, KDIM);
#pragma unroll
        for (int j = 0; j < 6; j++) {
            wmma::fragment<wmma::matrix_b, 16, 16, 16, __half, wmma::row_major> bf;
            wmma::load_matrix_sync(bf, Bs + k * 16 * DM + j * 16, DM);
            wmma::mma_sync(c[j], a, bf, c[j]);
        }
    }

#pragma unroll
    for (int half_id = 0; half_id < 2; half_id++) {
        int c0 = half_id * 48;
#pragma unroll
        for (int j = 0; j < 3; j++)
            wmma::store_matrix_sync(&stage[warp][j * 16], c[half_id * 3 + j], 48,
                                    wmma::mem_row_major);
        __syncwarp();
        // 16 rows x 48 cols = 16 x 24 half2
        for (int i = lane; i < 16 * 24; i += 32) {
            int r = i / 24, cp = i % 24;
            float v0 = stage[warp][r * 48 + 2 * cp];
            float v1 = stage[warp][r * 48 + 2 * cp + 1];
            int grow = row0 + r;
            if (EPI == 0) {
                float dn = g_dis[grow];
                ((__half2*)(g_h + (size_t)grow * DM + c0))[cp] =
                    __floats2half2_rn(v0 * dn, v1 * dn);
            } else {
                ((__half2*)(g_agg16 + (size_t)grow * DM + c0))[cp] =
                    __floats2half2_rn(lrelu(v0 + bias_s[c0 + 2 * cp]),
                                      lrelu(v1 + bias_s[c0 + 2 * cp + 1]));
            }
        }
        __syncwarp();
    }
}

// ---------------- gather: agg16 = lrelu(b + dis[d]*(h'[d] + sum h'[src])) ---
// fp16 rows (192B). 24 active lanes, float2 (4 features) per lane, unroll 8.
__global__ void gather_k(const float* __restrict__ b) {
    int w = (blockIdx.x * blockDim.x + threadIdx.x) >> 5;
    if (w >= N_NODES) return;
    int lane = threadIdx.x & 31;
    bool act = lane < 24;
    int beg = g_rowstart[w], end = g_rowstart[w + 1];
    float dn = g_dis[w];
    const float2* h2 = (const float2*)g_h;  // 24 float2 per row
    float4 acc = make_float4(0.f, 0.f, 0.f, 0.f);

#define ACC_ROW(raw) do {                                              \
        __half2 p0 = *reinterpret_cast<const __half2*>(&(raw).x);      \
        __half2 p1 = *reinterpret_cast<const __half2*>(&(raw).y);      \
        float2 f0 = __half22float2(p0), f1 = __half22float2(p1);       \
        acc.x += f0.x; acc.y += f0.y; acc.z += f1.x; acc.w += f1.y;    \
    } while (0)

    if (act) { float2 rw = __ldg(&h2[(size_t)w * 24 + lane]); ACC_ROW(rw); }
    int j = beg;
    for (; j + 7 < end; j += 8) {
        int s[8];
#pragma unroll
        for (int u = 0; u < 8; u++) s[u] = __ldg(&g_csr_src[j + u]);
        if (act) {
            float2 r[8];
#pragma unroll
            for (int u = 0; u < 8; u++) r[u] = __ldg(&h2[(size_t)s[u] * 24 + lane]);
#pragma unroll
            for (int u = 0; u < 8; u++) ACC_ROW(r[u]);
        }
    }
    for (; j + 1 < end; j += 2) {
        int s0 = __ldg(&g_csr_src[j]);
        int s1 = __ldg(&g_csr_src[j + 1]);
        if (act) {
            float2 r0 = __ldg(&h2[(size_t)s0 * 24 + lane]);
            float2 r1 = __ldg(&h2[(size_t)s1 * 24 + lane]);
            ACC_ROW(r0); ACC_ROW(r1);
        }
    }
    if (j < end) {
        int s = __ldg(&g_csr_src[j]);
        if (act) { float2 r = __ldg(&h2[(size_t)s * 24 + lane]); ACC_ROW(r); }
    }
#undef ACC_ROW

    if (act) {
        float4 bb = *(const float4*)(b + lane * 4);
        __half2 o0 = __floats2half2_rn(lrelu(fmaf(dn, acc.x, bb.x)),
                                       lrelu(fmaf(dn, acc.y, bb.y)));
        __half2 o1 = __floats2half2_rn(lrelu(fmaf(dn, acc.z, bb.z)),
                                       lrelu(fmaf(dn, acc.w, bb.w)));
        float2 pk;
        *reinterpret_cast<__half2*>(&pk.x) = o0;
        *reinterpret_cast<__half2*>(&pk.y) = o1;
        ((float2*)g_agg16)[(size_t)w * 24 + lane] = pk;
    }
}

// ---------------- fused tail: pooling + MLP1 + MLP2 (fp16 agg) --------------
__global__ void tail_k(const float* __restrict__ Wo1, const float* __restrict__ bo1,
                       const float* __restrict__ Wo2, const float* __restrict__ bo2,
                       float* __restrict__ out) {
    int g = blockIdx.x;
    int beg = g_goff[g], end = g_goff[g + 1];
    int t = threadIdx.x;                 // 288 threads = 3 x 96
    int f = t % DM, rr = t / DM;
    __shared__ float smx[288], ssm[288];
    __shared__ float pooled[2 * DM];
    __shared__ float hidden[DM];

    float mx = -INFINITY, sm = 0.0f;
    for (int n = beg + rr; n < end; n += 3) {
        float v = __half2float(g_agg16[(size_t)n * DM + f]);
        mx = fmaxf(mx, v);
        sm += v;
    }
    smx[t] = mx;
    ssm[t] = sm;
    __syncthreads();
    if (rr == 0) {
        mx = fmaxf(fmaxf(smx[f], smx[f + DM]), smx[f + 2 * DM]);
        sm = ssm[f] + ssm[f + DM] + ssm[f + 2 * DM];
        pooled[f] = mx;
        pooled[DM + f] = sm / fmaxf((float)(end - beg), 1.0f);
    }
    __syncthreads();
    if (t < DM) {
        float acc = bo1[t];
#pragma unroll 8
        for (int k = 0; k < 2 * DM; k++) acc = fmaf(pooled[k], Wo1[k * DM + t], acc);
        hidden[t] = lrelu(acc);
    }
    __syncthreads();
    if (t < 32) {
        float a = 0.0f;
#pragma unroll
        for (int k = t; k < DM; k += 32) a = fmaf(hidden[k], Wo2[k], a);
#pragma unroll
        for (int o = 16; o; o >>= 1) a += __shfl_down_sync(0xffffffff, a, o);
        if (t == 0) out[g] = a + bo2[0];
    }
}

// ---------------- host orchestration ---------------------------------------
extern "C" void kernel_launch(void* const* d_in, const int* in_sizes, int n_in,
                              void* d_out, int out_size) {
    const float* x      = (const float*)d_in[0];
    const void*  ei     = d_in[1];
    const void*  batch  = d_in[2];
    const float* W_init = (const float*)d_in[3];
    const float* b_init = (const float*)d_in[4];
    const float* Wl[4]  = {(const float*)d_in[5], (const float*)d_in[7],
                           (const float*)d_in[9], (const float*)d_in[11]};
    const float* bl[4]  = {(const float*)d_in[6], (const float*)d_in[8],
                           (const float*)d_in[10], (const float*)d_in[12]};
    const float* Wo1    = (const float*)d_in[13];
    const float* bo1    = (const float*)d_in[14];
    const float* Wo2    = (const float*)d_in[15];
    const float* bo2    = (const float*)d_in[16];
    float* out = (float*)d_out;

    __half* p_aggx16 = nullptr;
    __half* p_agg16 = nullptr;
    cudaGetSymbolAddress((void**)&p_aggx16, g_aggx16);
    cudaGetSymbolAddress((void**)&p_agg16, g_agg16);

    const int T = 256;
    const int gridE   = (N_EDGES + T - 1) / T;
    const int gridG   = (N_NODES * 32 + T - 1) / T;   // warp per node
    const int gridG16 = (N_NODES * 8 + T - 1) / T;    // 8 lanes per node
    const int gridMM  = N_PAD / 128;                  // 391

    init_k<<<NBLK_N, T>>>((const int*)ei);
    count_k<<<gridE, T>>>(ei, batch);
    scanpart_dis_k<<<NBLK_N, T>>>(x);
    scantop_goff_k<<<1, T>>>();
    scan_down_k<<<NBLK_N, T>>>();
    bucket_k<<<gridE, T>>>(ei);

    // layer 1: aggregate in 16-dim input space, then wmma GEMM + lrelu(+b)
    gather16_k<<<gridG16, T>>>();
    gemm_wmma_k<FIN0, 1><<<gridMM, 256>>>(p_aggx16, W_init, b_init);

    // layers 2..5 (K=96)
    for (int l = 0; l < 4; l++) {
        gemm_wmma_k<DM, 0><<<gridMM, 256>>>(p_agg16, Wl[l], nullptr);
        gather_k<<<gridG, T>>>(bl[l]);
    }

    // fused pooling + MLP head
    tail_k<<<NG, 288>>>(Wo1, bo1, Wo2, bo2, out);
}